// round 15
// baseline (speedup 1.0000x reference)
#include <cuda_runtime.h>

// SWAttention AV — R13/R11 skeleton + L2 evict_last (policy-operand form) on the
// reused bias/lt arrays. v stream: evict_first (single-use). q: default policy
// (latency-critical; hinting it regressed in R12). out: write-streaming __stcs.
// B=8, H=8, N=3136, D=32, K2=9. Block = 160 threads (5 warps), 16 rows/block.
//
// Phase 1: attn[n,k] = q[n,:]·lt[:,k] + bias + local   (thread per (n,k), 144 threads)
// Phase 2: out[n,d]  = sum_k attn[n,k]*v[n,d,k]        (warps 0-3, 4 rows each, 128-bit ops)

#define HH 8
#define NN 3136
#define NROWS (8 * HH * NN)       // 200704
#define TILE 16
#define NBLOCKS (NROWS / TILE)    // 12544
#define NTHREADS 160

__device__ __forceinline__ unsigned smem_u32(const void* p) {
    return (unsigned)__cvta_generic_to_shared(p);
}
__device__ __forceinline__ void cp16(unsigned dst, const void* src) {
    asm volatile("cp.async.cg.shared.global [%0], [%1], 16;" :: "r"(dst), "l"(src));
}
__device__ __forceinline__ void cp16_ef(unsigned dst, const void* src, unsigned long long pol) {
    asm volatile("cp.async.cg.shared.global.L2::cache_hint [%0], [%1], 16, %2;"
                 :: "r"(dst), "l"(src), "l"(pol));
}
__device__ __forceinline__ void cp_commit() {
    asm volatile("cp.async.commit_group;");
}
// Reused-data load: read-only path + L2 cache_hint with an evict_last policy operand
// (the immediate .L2::evict_last qualifier is illegal on scalar ld for sm_103a).
__device__ __forceinline__ float ldg_persist(const float* p, unsigned long long pol) {
    float r;
    asm volatile("ld.global.nc.L2::cache_hint.f32 %0, [%1], %2;"
                 : "=f"(r) : "l"(p), "l"(pol));
    return r;
}

__global__ __launch_bounds__(NTHREADS)
void swattn_kernel(const float* __restrict__ q,
                   const float* __restrict__ attn_local,
                   const float* __restrict__ v,
                   const float* __restrict__ lt,
                   const float* __restrict__ bias,
                   float* __restrict__ out) {
    __shared__ float sq[TILE * 36];    //  2304 B, padded rows (144B) -> conflict-free f4
    __shared__ float sv[TILE * 288];   // 18432 B, flat contiguous tile
    __shared__ float sltT[9 * 36];     //  1296 B, lt transposed [k][d], padded
    __shared__ float sa[TILE * 12];    //   768 B, attn tile

    const int t    = threadIdx.x;
    const int w    = t >> 5;
    const int lane = t & 31;

    const size_t R0  = (size_t)blockIdx.x * TILE;
    const int    hn0 = (int)(R0 % (HH * NN));
    const int    h   = hn0 / NN;

    // evict_first policy for the never-reused v stream; evict_last for reused bias/lt
    unsigned long long pol_ef, pol_el;
    asm("createpolicy.fractional.L2::evict_first.b64 %0, 1.0;" : "=l"(pol_ef));
    asm("createpolicy.fractional.L2::evict_last.b64 %0, 1.0;"  : "=l"(pol_el));

    // ---- Group A: q tile via cp.async (128 x 16B, padded dst, default L2 policy) ----
    if (t < TILE * 8)
        cp16(smem_u32(sq + (t >> 3) * 36 + (t & 7) * 4), q + R0 * 32 + t * 4);
    cp_commit();

    // ---- Group B: v tile via cp.async, evict_first (1152 x 16B, block-strided) ----
    {
        const float*   vg = v + R0 * 288;
        const unsigned sd = smem_u32(sv);
        #pragma unroll
        for (int c = t; c < TILE * 72; c += NTHREADS)
            cp16_ef(sd + c * 16, vg + c * 4, pol_ef);
    }
    cp_commit();

    // ---- Stage lt transposed (tiny, evict_last: reused 12544x): sltT[k][d] = lt[h][d][k] ----
    #pragma unroll
    for (int i = t; i < 288; i += NTHREADS) {
        const int d = i / 9, k = i - 9 * d;
        sltT[k * 36 + d] = ldg_persist(lt + h * 288 + i, pol_el);
    }

    // ---- bias (evict_last, reused 8x across batch) + local (streaming) ----
    float bl = 0.f;
    if (t < TILE * 9)
        bl = ldg_persist(bias + (size_t)hn0 * 9 + t, pol_el)
           + __ldcs(attn_local + R0 * 9 + t);

    asm volatile("cp.async.wait_group 1;");   // q done; v still streaming
    __syncthreads();

    // ---- Phase 1: attn (thread per (n,k), t < 144) ----
    if (t < TILE * 9) {
        const int n = t / 9, k = t - 9 * n;
        const float4* q4 = reinterpret_cast<const float4*>(sq + n * 36);
        const float4* l4 = reinterpret_cast<const float4*>(sltT + k * 36);
        float acc = bl;
        #pragma unroll
        for (int i = 0; i < 8; i++) {
            float4 qa = q4[i], lb = l4[i];
            acc = fmaf(qa.x, lb.x, acc);
            acc = fmaf(qa.y, lb.y, acc);
            acc = fmaf(qa.z, lb.z, acc);
            acc = fmaf(qa.w, lb.w, acc);
        }
        sa[n * 12 + k] = acc;
    }

    asm volatile("cp.async.wait_group 0;");   // v done
    __syncthreads();

    // ---- Phase 2: AV. Warps 0-3, rows 4w..4w+3. Lane: row = lane>>3, d-group = lane&7 ----
    if (w < 4) {
        const int row = (w << 2) + (lane >> 3);   // tile-local row 0..15
        const int g7  = lane & 7;

        const float* sar = sa + row * 12;
        const float4 A0 = reinterpret_cast<const float4*>(sar)[0];
        const float4 A1 = reinterpret_cast<const float4*>(sar)[1];
        const float a[9] = {A0.x, A0.y, A0.z, A0.w, A1.x, A1.y, A1.z, A1.w, sar[8]};

        // Lane's 36 contiguous floats = v[row][4*g7 .. 4*g7+3][0..8]; static (d,k) decode.
        const float4* wv4 = reinterpret_cast<const float4*>(sv + row * 288 + g7 * 36);
        float acc[4] = {0.f, 0.f, 0.f, 0.f};
        #pragma unroll
        for (int i = 0; i < 9; i++) {
            float4 wv = wv4[i];
            acc[(4 * i + 0) / 9] = fmaf(a[(4 * i + 0) % 9], wv.x, acc[(4 * i + 0) / 9]);
            acc[(4 * i + 1) / 9] = fmaf(a[(4 * i + 1) % 9], wv.y, acc[(4 * i + 1) / 9]);
            acc[(4 * i + 2) / 9] = fmaf(a[(4 * i + 2) % 9], wv.z, acc[(4 * i + 2) / 9]);
            acc[(4 * i + 3) / 9] = fmaf(a[(4 * i + 3) % 9], wv.w, acc[(4 * i + 3) / 9]);
        }

        const float4 o = make_float4(acc[0], acc[1], acc[2], acc[3]);
        __stcs(reinterpret_cast<float4*>(out + (R0 + row) * 32 + 4 * g7), o);
    }
}

extern "C" void kernel_launch(void* const* d_in, const int* in_sizes, int n_in,
                              void* d_out, int out_size) {
    const float* q          = (const float*)d_in[0];  // [B,H,N,D]
    const float* attn_local = (const float*)d_in[1];  // [B,H,N,K2]
    const float* v_local    = (const float*)d_in[2];  // [B,H,N,D,K2]
    const float* lt         = (const float*)d_in[3];  // [H,D,K2]
    const float* bias       = (const float*)d_in[4];  // [H,N,K2]
    float* out = (float*)d_out;                       // [B,H,N,D]

    swattn_kernel<<<NBLOCKS, NTHREADS>>>(q, attn_local, v_local, lt, bias, out);
}

// round 16
// speedup vs baseline: 1.0007x; 1.0007x over previous
#include <cuda_runtime.h>

// SWAttention AV — FINAL (locked R13/R11): two-phase cp.async skeleton + L2
// evict_first on the v stream only. q default policy (hinting it regressed),
// bias/lt default policy (L2 already absorbs their reuse; evict_last was neutral),
// out via write-streaming __stcs.
// B=8, H=8, N=3136, D=32, K2=9. Block = 160 threads (5 warps), 16 rows/block.
//
// Phase 1: attn[n,k] = q[n,:]·lt[:,k] + bias + local   (thread per (n,k), 144 threads)
// Phase 2: out[n,d]  = sum_k attn[n,k]*v[n,d,k]        (warps 0-3, 4 rows each, 128-bit ops)
//
// Measured: 43.0us, HBM 6.31TB/s (79% spec), rel_err 1.3e-7 — ~95% of the
// achievable-BW floor for the ~270MB of physical traffic this problem requires.

#define HH 8
#define NN 3136
#define NROWS (8 * HH * NN)       // 200704
#define TILE 16
#define NBLOCKS (NROWS / TILE)    // 12544
#define NTHREADS 160

__device__ __forceinline__ unsigned smem_u32(const void* p) {
    return (unsigned)__cvta_generic_to_shared(p);
}
__device__ __forceinline__ void cp16(unsigned dst, const void* src) {
    asm volatile("cp.async.cg.shared.global [%0], [%1], 16;" :: "r"(dst), "l"(src));
}
__device__ __forceinline__ void cp16_ef(unsigned dst, const void* src, unsigned long long pol) {
    asm volatile("cp.async.cg.shared.global.L2::cache_hint [%0], [%1], 16, %2;"
                 :: "r"(dst), "l"(src), "l"(pol));
}
__device__ __forceinline__ void cp_commit() {
    asm volatile("cp.async.commit_group;");
}

__global__ __launch_bounds__(NTHREADS)
void swattn_kernel(const float* __restrict__ q,
                   const float* __restrict__ attn_local,
                   const float* __restrict__ v,
                   const float* __restrict__ lt,
                   const float* __restrict__ bias,
                   float* __restrict__ out) {
    __shared__ float sq[TILE * 36];    //  2304 B, padded rows (144B) -> conflict-free f4
    __shared__ float sv[TILE * 288];   // 18432 B, flat contiguous tile
    __shared__ float sltT[9 * 36];     //  1296 B, lt transposed [k][d], padded
    __shared__ float sa[TILE * 12];    //   768 B, attn tile

    const int t    = threadIdx.x;
    const int w    = t >> 5;
    const int lane = t & 31;

    const size_t R0  = (size_t)blockIdx.x * TILE;
    const int    hn0 = (int)(R0 % (HH * NN));
    const int    h   = hn0 / NN;

    // evict_first policy for the never-reused v stream
    unsigned long long pol;
    asm("createpolicy.fractional.L2::evict_first.b64 %0, 1.0;" : "=l"(pol));

    // ---- Group A: q tile via cp.async (128 x 16B, padded dst, default L2 policy) ----
    if (t < TILE * 8)
        cp16(smem_u32(sq + (t >> 3) * 36 + (t & 7) * 4), q + R0 * 32 + t * 4);
    cp_commit();

    // ---- Group B: v tile via cp.async, evict_first (1152 x 16B, block-strided) ----
    {
        const float*   vg = v + R0 * 288;
        const unsigned sd = smem_u32(sv);
        #pragma unroll
        for (int c = t; c < TILE * 72; c += NTHREADS)
            cp16_ef(sd + c * 16, vg + c * 4, pol);
    }
    cp_commit();

    // ---- Stage lt transposed (tiny, L2-normal): sltT[k][d] = lt[h][d][k] ----
    #pragma unroll
    for (int i = t; i < 288; i += NTHREADS) {
        const int d = i / 9, k = i - 9 * d;
        sltT[k * 36 + d] = lt[h * 288 + i];
    }

    // ---- bias (L2-normal, reused 8x) + local (streaming) into register ----
    float bl = 0.f;
    if (t < TILE * 9)
        bl = bias[(size_t)hn0 * 9 + t] + __ldcs(attn_local + R0 * 9 + t);

    asm volatile("cp.async.wait_group 1;");   // q done; v still streaming
    __syncthreads();

    // ---- Phase 1: attn (thread per (n,k), t < 144) ----
    if (t < TILE * 9) {
        const int n = t / 9, k = t - 9 * n;
        const float4* q4 = reinterpret_cast<const float4*>(sq + n * 36);
        const float4* l4 = reinterpret_cast<const float4*>(sltT + k * 36);
        float acc = bl;
        #pragma unroll
        for (int i = 0; i < 8; i++) {
            float4 qa = q4[i], lb = l4[i];
            acc = fmaf(qa.x, lb.x, acc);
            acc = fmaf(qa.y, lb.y, acc);
            acc = fmaf(qa.z, lb.z, acc);
            acc = fmaf(qa.w, lb.w, acc);
        }
        sa[n * 12 + k] = acc;
    }

    asm volatile("cp.async.wait_group 0;");   // v done
    __syncthreads();

    // ---- Phase 2: AV. Warps 0-3, rows 4w..4w+3. Lane: row = lane>>3, d-group = lane&7 ----
    if (w < 4) {
        const int row = (w << 2) + (lane >> 3);   // tile-local row 0..15
        const int g7  = lane & 7;

        const float* sar = sa + row * 12;
        const float4 A0 = reinterpret_cast<const float4*>(sar)[0];
        const float4 A1 = reinterpret_cast<const float4*>(sar)[1];
        const float a[9] = {A0.x, A0.y, A0.z, A0.w, A1.x, A1.y, A1.z, A1.w, sar[8]};

        // Lane's 36 contiguous floats = v[row][4*g7 .. 4*g7+3][0..8]; static (d,k) decode.
        const float4* wv4 = reinterpret_cast<const float4*>(sv + row * 288 + g7 * 36);
        float acc[4] = {0.f, 0.f, 0.f, 0.f};
        #pragma unroll
        for (int i = 0; i < 9; i++) {
            float4 wv = wv4[i];
            acc[(4 * i + 0) / 9] = fmaf(a[(4 * i + 0) % 9], wv.x, acc[(4 * i + 0) / 9]);
            acc[(4 * i + 1) / 9] = fmaf(a[(4 * i + 1) % 9], wv.y, acc[(4 * i + 1) / 9]);
            acc[(4 * i + 2) / 9] = fmaf(a[(4 * i + 2) % 9], wv.z, acc[(4 * i + 2) / 9]);
            acc[(4 * i + 3) / 9] = fmaf(a[(4 * i + 3) % 9], wv.w, acc[(4 * i + 3) / 9]);
        }

        const float4 o = make_float4(acc[0], acc[1], acc[2], acc[3]);
        __stcs(reinterpret_cast<float4*>(out + (R0 + row) * 32 + 4 * g7), o);
    }
}

extern "C" void kernel_launch(void* const* d_in, const int* in_sizes, int n_in,
                              void* d_out, int out_size) {
    const float* q          = (const float*)d_in[0];  // [B,H,N,D]
    const float* attn_local = (const float*)d_in[1];  // [B,H,N,K2]
    const float* v_local    = (const float*)d_in[2];  // [B,H,N,D,K2]
    const float* lt         = (const float*)d_in[3];  // [H,D,K2]
    const float* bias       = (const float*)d_in[4];  // [H,N,K2]
    float* out = (float*)d_out;                       // [B,H,N,D]

    swattn_kernel<<<NBLOCKS, NTHREADS>>>(q, attn_local, v_local, lt, bias, out);
}

// round 17
// speedup vs baseline: 1.0551x; 1.0543x over previous
#include <cuda_runtime.h>

// SWAttention AV — R13 skeleton with the v tile moved to TMA bulk copy
// (cp.async.bulk, 1 instruction/block instead of 1152 LDGSTS), mbarrier completion,
// evict_first L2 hint preserved. q stays cp.async.cg (default policy), out __stcs.
// B=8, H=8, N=3136, D=32, K2=9. Block = 160 threads (5 warps), 16 rows/block.

#define HH 8
#define NN 3136
#define NROWS (8 * HH * NN)       // 200704
#define TILE 16
#define NBLOCKS (NROWS / TILE)    // 12544
#define NTHREADS 160
#define V_TILE_BYTES (TILE * 288 * 4)   // 18432

__device__ __forceinline__ unsigned smem_u32(const void* p) {
    return (unsigned)__cvta_generic_to_shared(p);
}
__device__ __forceinline__ void cp16(unsigned dst, const void* src) {
    asm volatile("cp.async.cg.shared.global [%0], [%1], 16;" :: "r"(dst), "l"(src));
}
__device__ __forceinline__ void cp_commit() {
    asm volatile("cp.async.commit_group;");
}

__global__ __launch_bounds__(NTHREADS)
void swattn_kernel(const float* __restrict__ q,
                   const float* __restrict__ attn_local,
                   const float* __restrict__ v,
                   const float* __restrict__ lt,
                   const float* __restrict__ bias,
                   float* __restrict__ out) {
    __shared__ float sq[TILE * 36];                 //  2304 B, padded, conflict-free f4
    __shared__ alignas(16) float sv[TILE * 288];    // 18432 B, TMA bulk destination
    __shared__ float sltT[9 * 36];                  //  1296 B, lt transposed, padded
    __shared__ float sa[TILE * 12];                 //   768 B, attn tile
    __shared__ alignas(8) unsigned long long mbar;  // TMA completion barrier

    const int t    = threadIdx.x;
    const int w    = t >> 5;
    const int lane = t & 31;

    const size_t R0  = (size_t)blockIdx.x * TILE;
    const int    hn0 = (int)(R0 % (HH * NN));
    const int    h   = hn0 / NN;

    // evict_first policy for the never-reused v stream
    unsigned long long pol;
    asm("createpolicy.fractional.L2::evict_first.b64 %0, 1.0;" : "=l"(pol));

    // ---- q tile via cp.async immediately (no barrier needed) ----
    if (t < TILE * 8)
        cp16(smem_u32(sq + (t >> 3) * 36 + (t & 7) * 4), q + R0 * 32 + t * 4);
    cp_commit();

    // ---- mbarrier init, then single TMA bulk copy for the whole v tile ----
    const unsigned mb = smem_u32(&mbar);
    if (t == 0)
        asm volatile("mbarrier.init.shared.b64 [%0], 1;" :: "r"(mb) : "memory");
    __syncthreads();                              // mbar visible before arrival
    if (t == 0) {
        asm volatile("mbarrier.arrive.expect_tx.shared.b64 _, [%0], %1;"
                     :: "r"(mb), "r"((unsigned)V_TILE_BYTES) : "memory");
        asm volatile(
            "cp.async.bulk.shared::cta.global.mbarrier::complete_tx::bytes.L2::cache_hint"
            " [%0], [%1], %2, [%3], %4;"
            :: "r"(smem_u32(sv)), "l"(v + R0 * 288),
               "r"((unsigned)V_TILE_BYTES), "r"(mb), "l"(pol)
            : "memory");
    }

    // ---- Stage lt transposed (tiny, L2-normal): sltT[k][d] = lt[h][d][k] ----
    #pragma unroll
    for (int i = t; i < 288; i += NTHREADS) {
        const int d = i / 9, k = i - 9 * d;
        sltT[k * 36 + d] = lt[h * 288 + i];
    }

    // ---- bias (L2-normal, reused 8x) + local (streaming) into register ----
    float bl = 0.f;
    if (t < TILE * 9)
        bl = bias[(size_t)hn0 * 9 + t] + __ldcs(attn_local + R0 * 9 + t);

    asm volatile("cp.async.wait_group 0;");       // q done; TMA v still flying
    __syncthreads();

    // ---- Phase 1: attn (thread per (n,k), t < 144) ----
    if (t < TILE * 9) {
        const int n = t / 9, k = t - 9 * n;
        const float4* q4 = reinterpret_cast<const float4*>(sq + n * 36);
        const float4* l4 = reinterpret_cast<const float4*>(sltT + k * 36);
        float acc = bl;
        #pragma unroll
        for (int i = 0; i < 8; i++) {
            float4 qa = q4[i], lb = l4[i];
            acc = fmaf(qa.x, lb.x, acc);
            acc = fmaf(qa.y, lb.y, acc);
            acc = fmaf(qa.z, lb.z, acc);
            acc = fmaf(qa.w, lb.w, acc);
        }
        sa[n * 12 + k] = acc;
    }
    __syncthreads();                              // sa visible across warps

    // ---- Wait for the TMA v tile (parity 0, acquire) ----
    {
        unsigned done;
        asm volatile(
            "{\n\t.reg .pred p;\n\t"
            "mbarrier.try_wait.parity.acquire.cta.shared::cta.b64 p, [%1], 0;\n\t"
            "selp.b32 %0, 1, 0, p;\n\t}"
            : "=r"(done) : "r"(mb) : "memory");
        if (!done) {
            asm volatile(
                "{\n\t.reg .pred P1;\n\t"
                "WL_%=:\n\t"
                "mbarrier.try_wait.parity.acquire.cta.shared::cta.b64 P1, [%0], 0, 0x989680;\n\t"
                "@P1 bra.uni WD_%=;\n\t"
                "bra.uni WL_%=;\n\t"
                "WD_%=:\n\t}"
                :: "r"(mb) : "memory");
        }
    }

    // ---- Phase 2: AV. Warps 0-3, rows 4w..4w+3. Lane: row = lane>>3, d-group = lane&7 ----
    if (w < 4) {
        const int row = (w << 2) + (lane >> 3);   // tile-local row 0..15
        const int g7  = lane & 7;

        const float* sar = sa + row * 12;
        const float4 A0 = reinterpret_cast<const float4*>(sar)[0];
        const float4 A1 = reinterpret_cast<const float4*>(sar)[1];
        const float a[9] = {A0.x, A0.y, A0.z, A0.w, A1.x, A1.y, A1.z, A1.w, sar[8]};

        // Lane's 36 contiguous floats = v[row][4*g7 .. 4*g7+3][0..8]; static (d,k) decode.
        const float4* wv4 = reinterpret_cast<const float4*>(sv + row * 288 + g7 * 36);
        float acc[4] = {0.f, 0.f, 0.f, 0.f};
        #pragma unroll
        for (int i = 0; i < 9; i++) {
            float4 wv = wv4[i];
            acc[(4 * i + 0) / 9] = fmaf(a[(4 * i + 0) % 9], wv.x, acc[(4 * i + 0) / 9]);
            acc[(4 * i + 1) / 9] = fmaf(a[(4 * i + 1) % 9], wv.y, acc[(4 * i + 1) / 9]);
            acc[(4 * i + 2) / 9] = fmaf(a[(4 * i + 2) % 9], wv.z, acc[(4 * i + 2) / 9]);
            acc[(4 * i + 3) / 9] = fmaf(a[(4 * i + 3) % 9], wv.w, acc[(4 * i + 3) / 9]);
        }

        const float4 o = make_float4(acc[0], acc[1], acc[2], acc[3]);
        __stcs(reinterpret_cast<float4*>(out + (R0 + row) * 32 + 4 * g7), o);
    }
}

extern "C" void kernel_launch(void* const* d_in, const int* in_sizes, int n_in,
                              void* d_out, int out_size) {
    const float* q          = (const float*)d_in[0];  // [B,H,N,D]
    const float* attn_local = (const float*)d_in[1];  // [B,H,N,K2]
    const float* v_local    = (const float*)d_in[2];  // [B,H,N,D,K2]
    const float* lt         = (const float*)d_in[3];  // [H,D,K2]
    const float* bias       = (const float*)d_in[4];  // [H,N,K2]
    float* out = (float*)d_out;                       // [B,H,N,D]

    swattn_kernel<<<NBLOCKS, NTHREADS>>>(q, attn_local, v_local, lt, bias, out);
}